// round 13
// baseline (speedup 1.0000x reference)
#include <cuda_runtime.h>
#include <cuda_fp16.h>
#include <cstdint>

#define NTHREADS 128

// ---- scratch (device globals: allocation-free) ----
__device__ float g_S[8 * 64 * 64];   // channel-summed image  S[b][i][j]
__device__ float g_T[8 * 64 * 64];   // 3x3 zero-pad box of S T[b][i][j]
__device__ float g_wsum[64];         // per-output weight sum

// pack (lo,hi) floats into half2 with lo in low 16 bits
__device__ __forceinline__ uint32_t packh2(float lo, float hi){
    uint32_t d;
    asm("cvt.rn.f16x2.f32 %0, %1, %2;" : "=r"(d) : "f"(hi), "f"(lo));
    return d;
}
// duplicated (v,v) half2 bits from one f32
__device__ __forceinline__ uint32_t f2dup(float v){
    uint32_t d;
    asm("cvt.rn.f16x2.f32 %0, %1, %1;" : "=r"(d) : "f"(v));
    return d;
}

__device__ __forceinline__ void cpasync16(uint32_t daddr, const float* g, int srcsize){
    asm volatile("cp.async.cg.shared.global [%0], [%1], 16, %2;"
                 :: "r"(daddr), "l"(g), "r"(srcsize));
}
__device__ __forceinline__ void cp_commit(){ asm volatile("cp.async.commit_group;"); }
template<int N> __device__ __forceinline__ void cp_wait(){
    asm volatile("cp.async.wait_group %0;" :: "n"(N));
}

// ---- prep kernel 1: S = sum_c x ; wsum[o] = sum_{c,taps} w ----
__global__ void prep_sum(const float* __restrict__ x, const float* __restrict__ w){
    int bx = blockIdx.x;
    if (bx < 128) {
        int id = bx * 256 + threadIdx.x;       // pixel index (b,i,j), 32768 total
        int b = id >> 12, rem = id & 4095;
        const float* p = x + b * 64 * 4096 + rem;
        float s = 0.0f;
        #pragma unroll 8
        for (int c = 0; c < 64; ++c) s += p[c * 4096];
        g_S[id] = s;
    } else if (threadIdx.x < 64) {
        const float* p = w + threadIdx.x * 576;
        float s = 0.0f;
        for (int k = 0; k < 576; ++k) s += p[k];
        g_wsum[threadIdx.x] = s;
    }
}

// ---- prep kernel 2: T = 3x3 zero-pad box filter of S ----
__global__ void prep_box(){
    int id = blockIdx.x * 256 + threadIdx.x;   // 32768
    int b = id >> 12, rem = id & 4095;
    int i = rem >> 6, j = rem & 63;
    float t = 0.0f;
    #pragma unroll
    for (int di = -1; di <= 1; ++di) {
        int ii = i + di;
        if ((unsigned)ii >= 64u) continue;
        #pragma unroll
        for (int dj = -1; dj <= 1; ++dj) {
            int jj = j + dj;
            if ((unsigned)jj >= 64u) continue;
            t += g_S[(b << 12) + (ii << 6) + jj];
        }
    }
    g_T[id] = t;
}

// Stripe tile: 64 wide x 4 tall, 8 output channels per CTA, channels chunked by 4.
// smem x tile row = 72 u32 cells; after in-place convert each holds dup half2.
#define ROWU 72
#define CHU  (6 * ROWU)
#define BUFU (4 * CHU)

__global__ __launch_bounds__(NTHREADS, 8)
void adder_kernel(const float* __restrict__ x,
                  const float* __restrict__ w,
                  const float* __restrict__ alpha,
                  float* __restrict__ out)
{
    __shared__ __align__(16) uint32_t s_xh[2 * BUFU];     // 13.8 KB double-buffered
    __shared__ __align__(16) uint32_t s_w2h[64 * 9 * 4];  // POSITIVE o-pair half2 weights 9.2 KB

    const int tid  = threadIdx.x;
    const int bx   = blockIdx.x;
    const int b    = bx >> 7;          // 8 batches
    const int st   = (bx >> 3) & 15;   // 16 row-stripes of 4
    const int ob   = bx & 7;           // 8 o-blocks (fastest: x L2 reuse)
    const int rloc = tid >> 5;         // 0..3 output row in stripe
    const int jp   = tid & 31;         // pair index; pixels j0=2jp, j0+1
    const int R0   = st * 4;

    const uint32_t sbase = (uint32_t)__cvta_generic_to_shared(s_xh);

    int u_ci[3], u_r[3], u_q[3];
    #pragma unroll
    for (int k = 0; k < 3; ++k) {
        int u = tid + k * NTHREADS;
        u_ci[k] = u / 96;
        int rem = u - u_ci[k] * 96;
        u_r[k] = rem >> 4;
        u_q[k] = rem & 15;
    }

    // ---- kick off chunk 0 loads ASAP ----
    #pragma unroll
    for (int k = 0; k < 3; ++k) {
        int gi = R0 - 1 + u_r[k];
        const float* src = x + (((b * 64 + u_ci[k]) * 64 + gi) * 64) + u_q[k] * 4;
        uint32_t dst = sbase + ((u_ci[k] * 6 + u_r[k]) * ROWU + 4 + u_q[k] * 4) * 4;
        cpasync16(dst, src, ((unsigned)gi < 64u) ? 16 : 0);
    }
    cp_commit();

    // ---- persistent halo-zero pads ----
    for (int u = tid; u < 96; u += NTHREADS) {
        int side = u & 1, rr = u >> 1;
        int buf = rr / 24, rem = rr - buf * 24;
        s_xh[buf * BUFU + rem * ROWU + (side ? 68 : 3)] = 0u;
    }

    // ---- stage POSITIVE o-pair half2 weights ----
    for (int e = tid; e < 64 * 9 * 4; e += NTHREADS) {
        int c   = e / 36;
        int r   = e - c * 36;
        int tap = r >> 2;
        int p   = r & 3;
        int o0  = ob * 8 + 2 * p;
        float lo = w[(o0 * 64 + c) * 9 + tap];
        float hi = w[((o0 + 1) * 64 + c) * 9 + tap];
        s_w2h[e] = packh2(lo, hi);
    }

    // fp32 master accumulators (hold Sum-of-max)
    float accF[2][8];
    #pragma unroll
    for (int p = 0; p < 2; ++p)
        #pragma unroll
        for (int o = 0; o < 8; ++o) accF[p][o] = 0.0f;

    // ---- prologue: finish chunk 0, bar, start chunk 1 ----
    cp_wait<0>();
    #pragma unroll
    for (int k = 0; k < 3; ++k) {
        uint32_t* cell = s_xh + (u_ci[k] * 6 + u_r[k]) * ROWU + 4 + u_q[k] * 4;
        float4 v = *(float4*)cell;
        uint4 o;
        o.x = f2dup(v.x); o.y = f2dup(v.y); o.z = f2dup(v.z); o.w = f2dup(v.w);
        *(uint4*)cell = o;
    }
    __syncthreads();
    #pragma unroll
    for (int k = 0; k < 3; ++k) {
        int gi = R0 - 1 + u_r[k];
        const float* src = x + (((b * 64 + 4 + u_ci[k]) * 64 + gi) * 64) + u_q[k] * 4;
        uint32_t dst = sbase + (BUFU + (u_ci[k] * 6 + u_r[k]) * ROWU + 4 + u_q[k] * 4) * 4;
        cpasync16(dst, src, ((unsigned)gi < 64u) ? 16 : 0);
    }
    cp_commit();

    #pragma unroll 1
    for (int ck = 0; ck < 16; ++ck) {
        // half2 chunk accumulators of max(x,w): <=36 terms per half
        __half2 acch[2][4];
        #pragma unroll
        for (int p = 0; p < 2; ++p)
            #pragma unroll
            for (int op = 0; op < 4; ++op) acch[p][op] = __half2half2(__ushort_as_half(0));

        const uint32_t* xb  = s_xh  + (ck & 1) * BUFU;
        const uint32_t* wcb = s_w2h + ck * 4 * 36;
        #pragma unroll 1
        for (int cc = 0; cc < 4; ++cc) {
            const uint32_t* wc = wcb + cc * 36;
            #pragma unroll
            for (int kh = 0; kh < 3; ++kh) {
                const uint32_t* xr = xb + cc * CHU + (rloc + kh) * ROWU;
                const uint2 A = *(const uint2*)(xr + 2 + 2 * jp);
                const uint2 B = *(const uint2*)(xr + 4 + 2 * jp);
                const uint32_t Cc = xr[6 + 2 * jp];
                uint32_t xb0 = A.y, xb1 = B.x, xb2 = B.y, xb3 = Cc;
                __half2 xh[4];
                xh[0] = *reinterpret_cast<__half2*>(&xb0);
                xh[1] = *reinterpret_cast<__half2*>(&xb1);
                xh[2] = *reinterpret_cast<__half2*>(&xb2);
                xh[3] = *reinterpret_cast<__half2*>(&xb3);
                #pragma unroll
                for (int kw = 0; kw < 3; ++kw) {
                    uint4 wq = *(const uint4*)(wc + (kh * 3 + kw) * 4);
                    const __half2 w0 = *reinterpret_cast<__half2*>(&wq.x);
                    const __half2 w1 = *reinterpret_cast<__half2*>(&wq.y);
                    const __half2 w2 = *reinterpret_cast<__half2*>(&wq.z);
                    const __half2 w3 = *reinterpret_cast<__half2*>(&wq.w);
                    // core: acc += max(x, w)  (HMNMX2 [alu?] + HADD2 [fma])
                    acch[0][0] = __hadd2(acch[0][0], __hmax2(xh[kw],     w0));
                    acch[1][0] = __hadd2(acch[1][0], __hmax2(xh[kw + 1], w0));
                    acch[0][1] = __hadd2(acch[0][1], __hmax2(xh[kw],     w1));
                    acch[1][1] = __hadd2(acch[1][1], __hmax2(xh[kw + 1], w1));
                    acch[0][2] = __hadd2(acch[0][2], __hmax2(xh[kw],     w2));
                    acch[1][2] = __hadd2(acch[1][2], __hmax2(xh[kw + 1], w2));
                    acch[0][3] = __hadd2(acch[0][3], __hmax2(xh[kw],     w3));
                    acch[1][3] = __hadd2(acch[1][3], __hmax2(xh[kw + 1], w3));
                }
            }
        }

        // ---- merge chunk (fp16 sum-of-max) into fp32 masters ----
        #pragma unroll
        for (int p = 0; p < 2; ++p)
            #pragma unroll
            for (int op = 0; op < 4; ++op) {
                accF[p][2 * op]     += __low2float(acch[p][op]);
                accF[p][2 * op + 1] += __high2float(acch[p][op]);
            }

        // ---- finish chunk ck+1: wait loads, convert own cells ----
        if (ck < 15) {
            cp_wait<0>();
            uint32_t* bnext = s_xh + ((ck + 1) & 1) * BUFU;
            #pragma unroll
            for (int k = 0; k < 3; ++k) {
                uint32_t* cell = bnext + (u_ci[k] * 6 + u_r[k]) * ROWU + 4 + u_q[k] * 4;
                float4 v = *(float4*)cell;
                uint4 o;
                o.x = f2dup(v.x); o.y = f2dup(v.y); o.z = f2dup(v.z); o.w = f2dup(v.w);
                *(uint4*)cell = o;
            }
        }
        __syncthreads();

        // ---- start chunk ck+2 ----
        if (ck < 14) {
            #pragma unroll
            for (int k = 0; k < 3; ++k) {
                int gi = R0 - 1 + u_r[k];
                const float* src = x + (((b * 64 + (ck + 2) * 4 + u_ci[k]) * 64 + gi) * 64) + u_q[k] * 4;
                uint32_t dst = sbase + ((ck & 1) * BUFU + (u_ci[k] * 6 + u_r[k]) * ROWU + 4 + u_q[k] * 4) * 4;
                cpasync16(dst, src, ((unsigned)gi < 64u) ? 16 : 0);
            }
            cp_commit();
        }
    }

    // ---- epilogue: Sum|x-w| = 2*SumMax - T - wsum;  y = x - Sum;  power ----
    const float a = alpha[0];
    const int gi  = R0 + rloc;
    const int j0  = 2 * jp;
    const int base = ((b * 64 + ob * 8) * 64 + gi) * 64 + j0;

    const float t0 = g_T[(b << 12) + (gi << 6) + j0];
    const float t1 = g_T[(b << 12) + (gi << 6) + j0 + 1];

    #pragma unroll
    for (int o = 0; o < 8; ++o) {
        const float ws = g_wsum[ob * 8 + o];
        const float2 xv = *(const float2*)(x + base + o * 4096);
        float s0 = 2.0f * accF[0][o] - t0 - ws;
        float s1 = 2.0f * accF[1][o] - t1 - ws;
        float y0 = xv.x - s0;
        float y1 = xv.y - s1;
        float r0, r1;
        if (a == 1.0f) { r0 = y0; r1 = y1; }
        else {
            r0 = copysignf(powf(fabsf(y0), a), y0);
            r1 = copysignf(powf(fabsf(y1), a), y1);
        }
        *(float2*)(out + base + o * 4096) = make_float2(r0, r1);
    }
}

extern "C" void kernel_launch(void* const* d_in, const int* in_sizes, int n_in,
                              void* d_out, int out_size)
{
    (void)in_sizes; (void)n_in; (void)out_size;
    const float* x     = (const float*)d_in[0];
    const float* wgt   = (const float*)d_in[1];
    const float* alpha = (const float*)d_in[2];
    float* out = (float*)d_out;
    prep_sum<<<129, 256>>>(x, wgt);      // S, wsum
    prep_box<<<128, 256>>>();            // T = box3(S)
    // grid: 8 batches * 16 row-stripes(64x4) * 8 o-blocks = 1024 CTAs
    adder_kernel<<<1024, NTHREADS>>>(x, wgt, alpha, out);
}

// round 15
// speedup vs baseline: 1.2858x; 1.2858x over previous
#include <cuda_runtime.h>
#include <cuda_fp16.h>
#include <cstdint>

#define NTHREADS 128

// pack (lo,hi) floats into half2 with lo in low 16 bits
__device__ __forceinline__ uint32_t packh2(float lo, float hi){
    uint32_t d;
    asm("cvt.rn.f16x2.f32 %0, %1, %2;" : "=r"(d) : "f"(hi), "f"(lo));
    return d;
}
// duplicated (v,v) half2 bits from one f32
__device__ __forceinline__ uint32_t f2dup(float v){
    uint32_t d;
    asm("cvt.rn.f16x2.f32 %0, %1, %1;" : "=r"(d) : "f"(v));
    return d;
}

__device__ __forceinline__ void cpasync16(uint32_t daddr, const float* g, int srcsize){
    asm volatile("cp.async.cg.shared.global [%0], [%1], 16, %2;"
                 :: "r"(daddr), "l"(g), "r"(srcsize));
}
__device__ __forceinline__ void cp_commit(){ asm volatile("cp.async.commit_group;"); }
template<int N> __device__ __forceinline__ void cp_wait(){
    asm volatile("cp.async.wait_group %0;" :: "n"(N));
}

// Stripe tile: 64 wide x 4 tall, 8 output channels per CTA, channels chunked by 4.
// x tile row = 72 u32 cells; after in-place convert each cell holds dup half2.
// idx 0..2 pad, idx 3 left halo zero, idx 4..67 cols 0..63, idx 68 right halo zero.
#define ROWU 72
#define CHU  (6 * ROWU)
#define BUFU (4 * CHU)
// Channel-sum tile S: 6 rows x 68 floats. Col j at idx j+2; left halo (j=-1) at
// idx 1, right halo (j=64) at idx 66. T = 3x3 zero-pad box of S.
#define SROW 68

__global__ __launch_bounds__(NTHREADS, 6)
void adder_kernel(const float* __restrict__ x,
                  const float* __restrict__ w,
                  const float* __restrict__ alpha,
                  float* __restrict__ out)
{
    __shared__ __align__(16) uint32_t s_xh[2 * BUFU];     // 13.8 KB double-buffered
    __shared__ __align__(16) uint32_t s_w2h[64 * 9 * 4];  // POSITIVE o-pair half2 weights 9.2 KB
    __shared__ __align__(16) float    s_S[6 * SROW];      // channel-sum tile 1.6 KB
    __shared__ float s_wspart[NTHREADS * 2];              // wsum partials 1 KB
    __shared__ float s_wsum[8];

    const int tid  = threadIdx.x;
    const int bx   = blockIdx.x;
    const int b    = bx >> 7;          // 8 batches
    const int st   = (bx >> 3) & 15;   // 16 row-stripes of 4
    const int ob   = bx & 7;           // 8 o-blocks (fastest: x L2 reuse)
    const int rloc = tid >> 5;         // 0..3 output row in stripe
    const int jp   = tid & 31;         // pair index; pixels j0=2jp, j0+1
    const int R0   = st * 4;

    const uint32_t sbase = (uint32_t)__cvta_generic_to_shared(s_xh);

    // per-thread unit decomposition: 3 units of 16 B (ci = channel-in-chunk)
    int u_ci[3], u_r[3], u_q[3];
    #pragma unroll
    for (int k = 0; k < 3; ++k) {
        int u = tid + k * NTHREADS;                // 0..383
        u_ci[k] = u / 96;
        int rem = u - u_ci[k] * 96;
        u_r[k] = rem >> 4;
        u_q[k] = rem & 15;
    }

    // ---- kick off chunk 0 loads ASAP ----
    #pragma unroll
    for (int k = 0; k < 3; ++k) {
        int gi = R0 - 1 + u_r[k];
        const float* src = x + (((b * 64 + u_ci[k]) * 64 + gi) * 64) + u_q[k] * 4;
        uint32_t dst = sbase + ((u_ci[k] * 6 + u_r[k]) * ROWU + 4 + u_q[k] * 4) * 4;
        cpasync16(dst, src, ((unsigned)gi < 64u) ? 16 : 0);
    }
    cp_commit();

    // ---- persistent halo-zero pads for x tile ----
    for (int u = tid; u < 96; u += NTHREADS) {
        int side = u & 1, rr = u >> 1;
        int buf = rr / 24, rem = rr - buf * 24;
        s_xh[buf * BUFU + rem * ROWU + (side ? 68 : 3)] = 0u;
    }

    // ---- stage POSITIVE o-pair half2 weights + wsum partials ----
    // stride NTHREADS => this thread's o-pair index p = tid&3 is constant, so
    // its f32 partial sums feed wsum[2p] / wsum[2p+1] directly.
    float ws_lo = 0.0f, ws_hi = 0.0f;
    for (int e = tid; e < 64 * 9 * 4; e += NTHREADS) {
        int c   = e / 36;
        int r   = e - c * 36;
        int tap = r >> 2;
        int p   = r & 3;
        int o0  = ob * 8 + 2 * p;
        float lo = w[(o0 * 64 + c) * 9 + tap];
        float hi = w[((o0 + 1) * 64 + c) * 9 + tap];
        ws_lo += lo; ws_hi += hi;
        s_w2h[e] = packh2(lo, hi);
    }
    s_wspart[tid * 2]     = ws_lo;
    s_wspart[tid * 2 + 1] = ws_hi;

    // fp32 master accumulators (hold Sum-of-max) + channel-sum partials
    float accF[2][8];
    #pragma unroll
    for (int p = 0; p < 2; ++p)
        #pragma unroll
        for (int o = 0; o < 8; ++o) accF[p][o] = 0.0f;
    float sreg[3][4];
    #pragma unroll
    for (int k = 0; k < 3; ++k)
        #pragma unroll
        for (int d = 0; d < 4; ++d) sreg[k][d] = 0.0f;

    // ---- prologue: finish chunk 0 (convert own cells, accumulate S), bar ----
    cp_wait<0>();
    #pragma unroll
    for (int k = 0; k < 3; ++k) {
        uint32_t* cell = s_xh + (u_ci[k] * 6 + u_r[k]) * ROWU + 4 + u_q[k] * 4;
        float4 v = *(float4*)cell;
        sreg[k][0] += v.x; sreg[k][1] += v.y; sreg[k][2] += v.z; sreg[k][3] += v.w;
        uint4 o;
        o.x = f2dup(v.x); o.y = f2dup(v.y); o.z = f2dup(v.z); o.w = f2dup(v.w);
        *(uint4*)cell = o;
    }
    __syncthreads();

    // wsum finalize: s_wsum[o] for o=0..7 (deterministic fixed-order reduce)
    if (tid < 8) {
        int p = tid >> 1, h = tid & 1;
        float s = 0.0f;
        for (int t = p; t < NTHREADS; t += 4) s += s_wspart[t * 2 + h];
        s_wsum[tid] = s;
    }

    // start chunk 1
    #pragma unroll
    for (int k = 0; k < 3; ++k) {
        int gi = R0 - 1 + u_r[k];
        const float* src = x + (((b * 64 + 4 + u_ci[k]) * 64 + gi) * 64) + u_q[k] * 4;
        uint32_t dst = sbase + (BUFU + (u_ci[k] * 6 + u_r[k]) * ROWU + 4 + u_q[k] * 4) * 4;
        cpasync16(dst, src, ((unsigned)gi < 64u) ? 16 : 0);
    }
    cp_commit();

    #pragma unroll 1
    for (int ck = 0; ck < 16; ++ck) {
        // half2 chunk accumulators of max(x,w): <=36 terms per half
        __half2 acch[2][4];
        #pragma unroll
        for (int p = 0; p < 2; ++p)
            #pragma unroll
            for (int op = 0; op < 4; ++op) acch[p][op] = __half2half2(__ushort_as_half(0));

        const uint32_t* xb  = s_xh  + (ck & 1) * BUFU;
        const uint32_t* wcb = s_w2h + ck * 4 * 36;
        #pragma unroll 1
        for (int cc = 0; cc < 4; ++cc) {
            const uint32_t* wc = wcb + cc * 36;
            #pragma unroll
            for (int kh = 0; kh < 3; ++kh) {
                const uint32_t* xr = xb + cc * CHU + (rloc + kh) * ROWU;
                const uint2 A = *(const uint2*)(xr + 2 + 2 * jp);   // (col j0-2, j0-1)
                const uint2 B = *(const uint2*)(xr + 4 + 2 * jp);   // (col j0,   j0+1)
                const uint32_t Cc = xr[6 + 2 * jp];                 //  col j0+2
                uint32_t xb0 = A.y, xb1 = B.x, xb2 = B.y, xb3 = Cc;
                __half2 xh[4];
                xh[0] = *reinterpret_cast<__half2*>(&xb0);
                xh[1] = *reinterpret_cast<__half2*>(&xb1);
                xh[2] = *reinterpret_cast<__half2*>(&xb2);
                xh[3] = *reinterpret_cast<__half2*>(&xb3);
                #pragma unroll
                for (int kw = 0; kw < 3; ++kw) {
                    uint4 wq = *(const uint4*)(wc + (kh * 3 + kw) * 4);
                    const __half2 w0 = *reinterpret_cast<__half2*>(&wq.x);
                    const __half2 w1 = *reinterpret_cast<__half2*>(&wq.y);
                    const __half2 w2 = *reinterpret_cast<__half2*>(&wq.z);
                    const __half2 w3 = *reinterpret_cast<__half2*>(&wq.w);
                    // core: acc += max(x, w)   (HMNMX2 alu + HADD2 fma)
                    acch[0][0] = __hadd2(acch[0][0], __hmax2(xh[kw],     w0));
                    acch[1][0] = __hadd2(acch[1][0], __hmax2(xh[kw + 1], w0));
                    acch[0][1] = __hadd2(acch[0][1], __hmax2(xh[kw],     w1));
                    acch[1][1] = __hadd2(acch[1][1], __hmax2(xh[kw + 1], w1));
                    acch[0][2] = __hadd2(acch[0][2], __hmax2(xh[kw],     w2));
                    acch[1][2] = __hadd2(acch[1][2], __hmax2(xh[kw + 1], w2));
                    acch[0][3] = __hadd2(acch[0][3], __hmax2(xh[kw],     w3));
                    acch[1][3] = __hadd2(acch[1][3], __hmax2(xh[kw + 1], w3));
                }
            }
        }

        // ---- merge chunk (fp16 sum-of-max) into fp32 masters ----
        #pragma unroll
        for (int p = 0; p < 2; ++p)
            #pragma unroll
            for (int op = 0; op < 4; ++op) {
                accF[p][2 * op]     += __low2float(acch[p][op]);
                accF[p][2 * op + 1] += __high2float(acch[p][op]);
            }

        // ---- finish chunk ck+1: wait loads, convert own cells, accumulate S ----
        if (ck < 15) {
            cp_wait<0>();
            uint32_t* bnext = s_xh + ((ck + 1) & 1) * BUFU;
            #pragma unroll
            for (int k = 0; k < 3; ++k) {
                uint32_t* cell = bnext + (u_ci[k] * 6 + u_r[k]) * ROWU + 4 + u_q[k] * 4;
                float4 v = *(float4*)cell;
                sreg[k][0] += v.x; sreg[k][1] += v.y; sreg[k][2] += v.z; sreg[k][3] += v.w;
                uint4 o;
                o.x = f2dup(v.x); o.y = f2dup(v.y); o.z = f2dup(v.z); o.w = f2dup(v.w);
                *(uint4*)cell = o;
            }
        }
        __syncthreads();

        // ---- start chunk ck+2 ----
        if (ck < 14) {
            #pragma unroll
            for (int k = 0; k < 3; ++k) {
                int gi = R0 - 1 + u_r[k];
                const float* src = x + (((b * 64 + (ck + 2) * 4 + u_ci[k]) * 64 + gi) * 64) + u_q[k] * 4;
                uint32_t dst = sbase + ((ck & 1) * BUFU + (u_ci[k] * 6 + u_r[k]) * ROWU + 4 + u_q[k] * 4) * 4;
                cpasync16(dst, src, ((unsigned)gi < 64u) ? 16 : 0);
            }
            cp_commit();
        }
    }

    // ---- deterministic S reduction: 4 passes over ci (pass 0 stores/init) ----
    if (tid < 12) {       // zero the column halos (j=-1 at idx 1, j=64 at idx 66)
        int r = tid >> 1, side = tid & 1;
        s_S[r * SROW + (side ? 66 : 1)] = 0.0f;
    }
    #pragma unroll
    for (int pass = 0; pass < 4; ++pass) {
        #pragma unroll
        for (int k = 0; k < 3; ++k) {
            if (u_ci[k] == pass) {
                float* cell = &s_S[u_r[k] * SROW + u_q[k] * 4 + 2];
                if (pass == 0) {
                    cell[0] = sreg[k][0]; cell[1] = sreg[k][1];
                    cell[2] = sreg[k][2]; cell[3] = sreg[k][3];
                } else {
                    cell[0] += sreg[k][0]; cell[1] += sreg[k][1];
                    cell[2] += sreg[k][2]; cell[3] += sreg[k][3];
                }
            }
        }
        __syncthreads();
    }

    // ---- epilogue: T = box3(S);  Sum|x-w| = 2*SumMax - T - wsum;  power ----
    const float a = alpha[0];
    const int gi  = R0 + rloc;
    const int j0  = 2 * jp;
    const int base = ((b * 64 + ob * 8) * 64 + gi) * 64 + j0;

    float T0 = 0.0f, T1 = 0.0f;
    #pragma unroll
    for (int kh = 0; kh < 3; ++kh) {
        const float* sr = s_S + (rloc + kh) * SROW;
        float2 a01 = *(const float2*)(sr + j0);       // idx j0,   j0+1
        float2 a23 = *(const float2*)(sr + j0 + 2);   // idx j0+2, j0+3
        float2 a45 = *(const float2*)(sr + j0 + 4);   // idx j0+4, j0+5
        T0 += a01.y + a23.x + a23.y;   // cols j0-1, j0,   j0+1
        T1 += a23.x + a23.y + a45.x;   // cols j0,   j0+1, j0+2
    }

    #pragma unroll
    for (int o = 0; o < 8; ++o) {
        const float ws = s_wsum[o];
        const float2 xv = *(const float2*)(x + base + o * 4096);
        float s0 = 2.0f * accF[0][o] - T0 - ws;
        float s1 = 2.0f * accF[1][o] - T1 - ws;
        float y0 = xv.x - s0;
        float y1 = xv.y - s1;
        float r0, r1;
        if (a == 1.0f) { r0 = y0; r1 = y1; }
        else {
            r0 = copysignf(powf(fabsf(y0), a), y0);
            r1 = copysignf(powf(fabsf(y1), a), y1);
        }
        *(float2*)(out + base + o * 4096) = make_float2(r0, r1);
    }
}

extern "C" void kernel_launch(void* const* d_in, const int* in_sizes, int n_in,
                              void* d_out, int out_size)
{
    (void)in_sizes; (void)n_in; (void)out_size;
    const float* x     = (const float*)d_in[0];
    const float* wgt   = (const float*)d_in[1];
    const float* alpha = (const float*)d_in[2];
    float* out = (float*)d_out;
    // grid: 8 batches * 16 row-stripes(64x4) * 8 o-blocks = 1024 CTAs
    adder_kernel<<<1024, NTHREADS>>>(x, wgt, alpha, out);
}